// round 14
// baseline (speedup 1.0000x reference)
#include <cuda_runtime.h>
#include <cuda_fp16.h>
#include <math.h>
#include <stdint.h>

// Problem constants
#define Hdim 512
#define Lsteps 16
#define Nrows 8192
#define NH (Nrows * Hdim)

// Panel: 128 rows x 64 fp16, 144B pitch (16B pad) = exact smem stage layout
#define PANEL_H 9216                    // halves per panel
#define PANEL_BYTES 18432
#define STG_BYTES 36864                 // A panel + B panel
#define NSTAGE 3
#define SMEM_BYTES (64 + NSTAGE * STG_BYTES)   // 110656

// ---------------- scratch (device globals) ------------------------------------
__device__ __half g_P[Lsteps * (size_t)NH];     // row-major, includes +C0
__device__ __half g_C0[NH];                     // row-major (x0@W3 + b_xi)
__device__ __half g_U[NH];                      // row-major
__device__ __half g_E16[75497472];              // panels
__device__ __half g_N16[80216064];              // panels (17 layers)
__device__ __half g_X0H16[4718592];
__device__ __half g_XTH16[4718592];
__device__ __half g_RH16[4718592];
__device__ __half g_HX16[4718592];              // fp16 recurrent state (panels)
__device__ __half g_W1T[294912];
__device__ __half g_WpT[589824];
__device__ __half g_W3T[294912];
__device__ __half g_WurT[1769472];
__device__ __half g_WkT[884736];

// ---------------- helpers -------------------------------------------------------
__device__ __forceinline__ uint32_t smem_u32(const void* p) {
    uint32_t a;
    asm("{ .reg .u64 t; cvta.to.shared.u64 t, %1; cvt.u32.u64 %0, t; }" : "=r"(a) : "l"(p));
    return a;
}
#define MBARRIER_INIT(addr, cnt) \
    asm volatile("mbarrier.init.shared.b64 [%0], %1;" :: "r"((uint32_t)(addr)), "r"((uint32_t)(cnt)) : "memory")
#define MBARRIER_EXPECT_TX(addr, tx) \
    asm volatile("mbarrier.arrive.expect_tx.shared.b64 _, [%0], %1;" :: "r"((uint32_t)(addr)), "r"((uint32_t)(tx)) : "memory")
#define MBARRIER_ARRIVE(addr) \
    asm volatile("mbarrier.arrive.shared.b64 _, [%0];" :: "r"((uint32_t)(addr)) : "memory")
#define MBARRIER_WAIT_PARITY(addr, par) do { \
    uint32_t _m = (uint32_t)(addr); uint32_t _p = (uint32_t)(par); uint32_t _d; \
    asm volatile("{\n\t.reg .pred p;\n\t" \
        "mbarrier.try_wait.parity.acquire.cta.shared::cta.b64 p, [%1], %2;\n\t" \
        "selp.b32 %0, 1, 0, p;\n\t}" : "=r"(_d) : "r"(_m), "r"(_p) : "memory"); \
    if (!_d) { \
        asm volatile("{\n\t.reg .pred P1;\n\t" \
            "WL_%=:\n\t" \
            "mbarrier.try_wait.parity.acquire.cta.shared::cta.b64 P1, [%0], %1, 0x989680;\n\t" \
            "@P1 bra.uni WD_%=;\n\t" \
            "bra.uni WL_%=;\n\t" \
            "WD_%=:\n\t}" :: "r"(_m), "r"(_p) : "memory"); \
    } } while (0)

__device__ __forceinline__ void bulk_cp(uint32_t dst, const void* src, uint32_t bytes,
                                        uint32_t mbar) {
    asm volatile(
        "cp.async.bulk.shared::cluster.global.mbarrier::complete_tx::bytes "
        "[%0], [%1], %2, [%3];"
        :: "r"(dst), "l"(src), "r"(bytes), "r"(mbar) : "memory");
}

__device__ __forceinline__ void ldsm_x4(uint32_t (&r)[4], uint32_t addr) {
    asm volatile("ldmatrix.sync.aligned.m8n8.x4.shared.b16 {%0,%1,%2,%3}, [%4];"
                 : "=r"(r[0]), "=r"(r[1]), "=r"(r[2]), "=r"(r[3]) : "r"(addr));
}
__device__ __forceinline__ void mma_f16(float (&d)[4], const uint32_t (&a)[4],
                                        uint32_t b0, uint32_t b1) {
    asm volatile(
        "mma.sync.aligned.m16n8k16.row.col.f32.f16.f16.f32 "
        "{%0,%1,%2,%3}, {%4,%5,%6,%7}, {%8,%9}, {%0,%1,%2,%3};"
        : "+f"(d[0]), "+f"(d[1]), "+f"(d[2]), "+f"(d[3])
        : "r"(a[0]), "r"(a[1]), "r"(a[2]), "r"(a[3]), "r"(b0), "r"(b1));
}
__device__ __forceinline__ float sigmoidf_(float x) { return 1.0f / (1.0f + expf(-x)); }
__device__ __forceinline__ float2 h2f(const __half* p) {
    return __half22float2(*(const __half2*)p);
}
__device__ __forceinline__ size_t pidx(int row, int col) {
    return ((size_t)((row >> 7) * 8 + (col >> 6))) * PANEL_H + (row & 127) * 72 + (col & 63);
}

// ---------------- GEMM ------------------------------------------------------------
struct GemmArgs {
    const __half* A[3];
    const __half* Bt;
    int kpb;
    int kb0;
    const __half* P;
    const __half* C0;
    const __half* x0;
    const __half* xl;
    const __half* hxp;
    const float* bias0;
    const float* bias1;
    const __half* U;
    float* out0;
    __half* out16a;
    __half* out16b;
};

#define MODE_PRE 0
#define MODE_C0  1
#define MODE_XI  2
#define MODE_UR  3
#define MODE_K   4

template <int MODE>
__device__ __forceinline__ void epi(const GemmArgs& g, int row, int col, float v0, float v1) {
    int c512 = col & 511;
    size_t idx = (size_t)row * Hdim + c512;
    if (MODE == MODE_PRE) {
        float2 c0v = h2f(g.C0 + (size_t)(row & (Nrows - 1)) * Hdim + c512);
        *(__half2*)(g.out16a + idx) = __floats2half2_rn(v0 + c0v.x, v1 + c0v.y);
    } else if (MODE == MODE_C0) {
        float2 b = *(const float2*)(g.bias0 + c512);
        *(__half2*)(g.out16a + idx) = __floats2half2_rn(v0 + b.x, v1 + b.y);
    } else if (MODE == MODE_XI) {
        size_t pp = pidx(row, c512);
        float2 p   = h2f(g.P  + idx);
        float2 x0v = h2f(g.x0 + pp);
        float2 xlv = h2f(g.xl + pp);
        float s0 = sigmoidf_(v0 + p.x);
        float s1 = sigmoidf_(v1 + p.y);
        *(__half2*)(g.out16a + pp) = __floats2half2_rn((1.f - s0) * x0v.x, (1.f - s1) * x0v.y);
        *(__half2*)(g.out16b + pp) = __floats2half2_rn(s0 * xlv.x, s1 * xlv.y);
    } else if (MODE == MODE_UR) {
        if (col < Hdim) {
            float2 b = *(const float2*)(g.bias0 + c512);
            *(__half2*)(g.out16a + idx) = __floats2half2_rn(sigmoidf_(v0 + b.x),
                                                            sigmoidf_(v1 + b.y));
        } else {
            size_t pp = pidx(row, c512);
            float2 b = *(const float2*)(g.bias1 + c512);
            float2 h = h2f(g.hxp + pp);
            *(__half2*)(g.out16b + pp) =
                __floats2half2_rn(sigmoidf_(v0 + b.x) * h.x, sigmoidf_(v1 + b.y) * h.y);
        }
    } else { // MODE_K
        size_t pp = pidx(row, c512);
        float2 b = *(const float2*)(g.bias0 + c512);
        float2 u = h2f(g.U + idx);
        float2 h = h2f(g.hxp + pp);
        float k0 = tanhf(v0 + b.x), k1 = tanhf(v1 + b.y);
        float r0 = (1.f - u.x) * k0 + u.x * h.x;
        float r1 = (1.f - u.y) * k1 + u.y * h.y;
        *(__half2*)(g.out16a + pp) = __floats2half2_rn(r0, r1);
        if (g.out0)
            *(float2*)(g.out0 + idx) = make_float2(r0, r1);
    }
}

__device__ __forceinline__ void issue_chunk(const GemmArgs& g, int kb, int m_tile, int n_tile,
                                            uint32_t dst, uint32_t mbar) {
    MBARRIER_EXPECT_TX(mbar, STG_BYTES);
    const __half* srcA = g.A[kb >> 3] + ((size_t)m_tile * 8 + (kb & 7)) * PANEL_H;
    const __half* srcB = g.Bt + ((size_t)n_tile * g.kpb + g.kb0 + kb) * PANEL_H;
    bulk_cp(dst, srcA, PANEL_BYTES, mbar);
    bulk_cp(dst + PANEL_BYTES, srcB, PANEL_BYTES, mbar);
}

__device__ __forceinline__ void compute_stage(uint32_t base, uint32_t a_off, uint32_t b_off,
                                              float (&acc)[4][4][4]) {
#pragma unroll
    for (int kk = 0; kk < 4; ++kk) {
        uint32_t a[4][4];
        uint32_t b[2][4];
#pragma unroll
        for (int i = 0; i < 4; ++i)
            ldsm_x4(a[i], base + a_off + kk * 32 + i * (16 * 144));
#pragma unroll
        for (int jj = 0; jj < 2; ++jj)
            ldsm_x4(b[jj], base + b_off + kk * 32 + jj * (16 * 144));
#pragma unroll
        for (int i = 0; i < 4; ++i)
#pragma unroll
            for (int j = 0; j < 4; ++j)
                mma_f16(acc[i][j], a[i], b[j >> 1][(j & 1) * 2], b[j >> 1][(j & 1) * 2 + 1]);
    }
}

// ---- streaming GEMM: one CTA processes T output tiles as one continuous kb stream
template <int MODE>
__global__ void __launch_bounds__(256, 2) gemm_stream(GemmArgs args, int kblocks,
                                                      int T, int nstep) {
    extern __shared__ char sm[];
    uint32_t su = smem_u32(sm);
    int tid = threadIdx.x;
    int warp = tid >> 5, lane = tid & 31;
    int MW = (warp & 1) * 64, NW = (warp >> 1) * 32;
    int g = lane >> 2, c = lane & 3;
    int m_tile = blockIdx.y, n0 = blockIdx.x;
    int rowBase = m_tile * 128;
    int total = T * kblocks;

    if (tid == 0) {
        MBARRIER_INIT(su + 0, 1);  MBARRIER_INIT(su + 8, 1);  MBARRIER_INIT(su + 16, 1);
        MBARRIER_INIT(su + 24, 8); MBARRIER_INIT(su + 32, 8); MBARRIER_INIT(su + 40, 8);
    }
    __syncthreads();

    uint32_t a_off = (uint32_t)((MW + (lane & 15)) * 144 + (lane >> 4) * 16);
    uint32_t b_off = (uint32_t)(PANEL_BYTES + (NW + (lane & 7) + ((lane >> 4) << 3)) * 144
                                + ((lane >> 3) & 1) * 16);

    float acc[4][4][4];
#pragma unroll
    for (int i = 0; i < 4; ++i)
#pragma unroll
        for (int j = 0; j < 4; ++j)
#pragma unroll
            for (int e = 0; e < 4; ++e) acc[i][j][e] = 0.0f;

    if (tid == 0) {
        int ni = total < NSTAGE ? total : NSTAGE;
        for (int s = 0; s < ni; ++s) {
            int tj = s / kblocks, kb = s - tj * kblocks;
            issue_chunk(args, kb, m_tile, n0 + nstep * tj,
                        su + 64 + s * STG_BYTES, su + 8 * s);
        }
    }

    int cs = 0, cp = 0;
    int ps = 0, pp = 0;
    for (int i = 0; i < total; ++i) {
        MBARRIER_WAIT_PARITY(su + 8 * cs, cp);
        compute_stage(su + 64 + cs * STG_BYTES, a_off, b_off, acc);
        if (lane == 0) MBARRIER_ARRIVE(su + 24 + 8 * cs);
        if (tid == 0 && i + NSTAGE < total) {
            MBARRIER_WAIT_PARITY(su + 24 + 8 * ps, pp);
            int j = i + NSTAGE;
            int tj = j / kblocks, kb = j - tj * kblocks;
            issue_chunk(args, kb, m_tile, n0 + nstep * tj,
                        su + 64 + ps * STG_BYTES, su + 8 * ps);
            if (++ps == NSTAGE) { ps = 0; pp ^= 1; }
        }
        if (++cs == NSTAGE) { cs = 0; cp ^= 1; }

        if (((i + 1) % kblocks) == 0) {
            int tt = i / kblocks;
            int colBase = (n0 + nstep * tt) * 128;
#pragma unroll
            for (int ii = 0; ii < 4; ++ii) {
#pragma unroll
                for (int j = 0; j < 4; ++j) {
                    int row = rowBase + MW + ii * 16 + g;
                    int col = colBase + NW + j * 8 + 2 * c;
                    epi<MODE>(args, row, col, acc[ii][j][0], acc[ii][j][1]);
                    epi<MODE>(args, row + 8, col, acc[ii][j][2], acc[ii][j][3]);
                }
            }
            if (i + 1 < total) {
#pragma unroll
                for (int ii = 0; ii < 4; ++ii)
#pragma unroll
                    for (int j = 0; j < 4; ++j)
#pragma unroll
                        for (int e = 0; e < 4; ++e) acc[ii][j][e] = 0.0f;
            }
        }
    }
}

// ---------------- step-0 XI elementwise (hx0 == 0 -> no GEMM) ---------------------
__global__ void xi0_kernel(const __half* __restrict__ P0,
                           const __half* __restrict__ x0p, const __half* __restrict__ xlp,
                           __half* __restrict__ X0H, __half* __restrict__ XTH) {
    int i = (blockIdx.x * blockDim.x + threadIdx.x) * 8;
    int row = i >> 9, col = i & 511;
    size_t pp = pidx(row, col);
    size_t idx = (size_t)row * Hdim + col;
    uint4 pv = *(const uint4*)(P0 + idx);
    uint4 xv = *(const uint4*)(x0p + pp);
    uint4 lv = *(const uint4*)(xlp + pp);
    const __half2* ph = (const __half2*)&pv;
    const __half2* xh = (const __half2*)&xv;
    const __half2* lh = (const __half2*)&lv;
    uint4 o0, o1;
    __half2* o0h = (__half2*)&o0;
    __half2* o1h = (__half2*)&o1;
#pragma unroll
    for (int q = 0; q < 4; ++q) {
        float2 p = __half22float2(ph[q]);
        float2 x = __half22float2(xh[q]);
        float2 l = __half22float2(lh[q]);
        float s0 = sigmoidf_(p.x);
        float s1 = sigmoidf_(p.y);
        o0h[q] = __floats2half2_rn((1.f - s0) * x.x, (1.f - s1) * x.y);
        o1h[q] = __floats2half2_rn(s0 * l.x, s1 * l.y);
    }
    *(uint4*)(X0H + pp) = o0;
    *(uint4*)(XTH + pp) = o1;
}

// ---------------- weight transpose into panels -----------------------------------
struct TransJobs {
    const float* src[7];
    __half* dst[7];
    int kpb[7];
    int nbase[7];
    int kbase[7];
    int ktiles[7];
    int tileofs[7];
};

__global__ void transposeAll(TransJobs J) {
    __shared__ float t[32][33];
    int bid = blockIdx.x;
    int job = 0;
#pragma unroll
    for (int i = 1; i < 7; ++i)
        if (bid >= J.tileofs[i]) job = i;
    int local = bid - J.tileofs[job];
    int kt = J.ktiles[job];
    int kb = (local % kt) * 32;
    int nb = (local / kt) * 32;
    const float* src = J.src[job];
    __half* dst = J.dst[job];
    int KPB = J.kpb[job];
    int tx = threadIdx.x, ty = threadIdx.y;
#pragma unroll
    for (int i = 0; i < 32; i += 8)
        t[ty + i][tx] = src[(size_t)(kb + ty + i) * 512 + nb + tx];
    __syncthreads();
    int k = J.kbase[job] + kb + tx;
#pragma unroll
    for (int i = 0; i < 32; i += 8) {
        int n = J.nbase[job] + nb + ty + i;
        size_t off = ((size_t)((n >> 7) * KPB + (k >> 6))) * PANEL_H + (n & 127) * 72 + (k & 63);
        dst[off] = __float2half_rn(t[tx][ty + i]);
    }
}

// ---------------- fp32 -> fp16 convert into panels --------------------------------
__global__ void f2h_panel(const float* __restrict__ src, __half* __restrict__ dst, int n) {
    int i = (blockIdx.x * blockDim.x + threadIdx.x) * 8;
    if (i >= n) return;
    float4 v0 = *(const float4*)(src + i);
    float4 v1 = *(const float4*)(src + i + 4);
    __half2 h[4] = {__floats2half2_rn(v0.x, v0.y), __floats2half2_rn(v0.z, v0.w),
                    __floats2half2_rn(v1.x, v1.y), __floats2half2_rn(v1.z, v1.w)};
    int row = i >> 9, col = i & 511;
    size_t off = ((size_t)((row >> 7) * 8 + (col >> 6))) * PANEL_H + (row & 127) * 72 + (col & 63);
    *(uint4*)(dst + off) = *(uint4*)h;
}

// ---------------- host --------------------------------------------------------------
template <int MODE>
static void run_stream(const GemmArgs& a, int gx, int gy, int kblocks, int T, int nstep) {
    cudaFuncSetAttribute(gemm_stream<MODE>, cudaFuncAttributeMaxDynamicSharedMemorySize,
                         SMEM_BYTES);
    dim3 grid(gx, gy);
    gemm_stream<MODE><<<grid, 256, SMEM_BYTES>>>(a, kblocks, T, nstep);
}

extern "C" void kernel_launch(void* const* d_in, const int* in_sizes, int n_in,
                              void* d_out, int out_size) {
    const float* edge = (const float*)d_in[0];
    const float* node = (const float*)d_in[1];
    const float* W_xi = (const float*)d_in[2];
    const float* b_xi = (const float*)d_in[3];
    const float* W_u  = (const float*)d_in[4];
    const float* b_u  = (const float*)d_in[5];
    const float* W_r  = (const float*)d_in[6];
    const float* b_r  = (const float*)d_in[7];
    const float* W_k  = (const float*)d_in[8];
    const float* b_k  = (const float*)d_in[9];
    float* hx = (float*)d_out;

    __half *P, *C0, *U;
    __half *E16, *N16, *X0H16, *XTH16, *RH16, *HX16, *W1T, *WpT, *W3T, *WurT, *WkT;
    cudaGetSymbolAddress((void**)&P,     g_P);
    cudaGetSymbolAddress((void**)&C0,    g_C0);
    cudaGetSymbolAddress((void**)&U,     g_U);
    cudaGetSymbolAddress((void**)&E16,   g_E16);
    cudaGetSymbolAddress((void**)&N16,   g_N16);
    cudaGetSymbolAddress((void**)&X0H16, g_X0H16);
    cudaGetSymbolAddress((void**)&XTH16, g_XTH16);
    cudaGetSymbolAddress((void**)&RH16,  g_RH16);
    cudaGetSymbolAddress((void**)&HX16,  g_HX16);
    cudaGetSymbolAddress((void**)&W1T,   g_W1T);
    cudaGetSymbolAddress((void**)&WpT,   g_WpT);
    cudaGetSymbolAddress((void**)&W3T,   g_W3T);
    cudaGetSymbolAddress((void**)&WurT,  g_WurT);
    cudaGetSymbolAddress((void**)&WkT,   g_WkT);

    cudaMemsetAsync(HX16, 0, sizeof(g_HX16), 0);

    // fp32 -> fp16 panels for edge / node (incl. x0)
    {
        int nE = Lsteps * NH;
        int nN = (Lsteps + 1) * NH;
        f2h_panel<<<(nE / 8 + 255) / 256, 256>>>(edge, E16, nE);
        f2h_panel<<<(nN / 8 + 255) / 256, 256>>>(node, N16, nN);
    }

    // weight transpose -> fp16 panels
    {
        TransJobs J;
        const float* srcs[7] = {W_xi, W_xi + 512 * 512, W_xi + 1536 * 512,
                                W_xi + 1024 * 512, W_u, W_r, W_k};
        __half* dsts[7] = {W1T, WpT, WpT, W3T, WurT, WurT, WkT};
        int kpbs[7]  = {8, 16, 16, 8, 24, 24, 24};
        int nbases[7] = {0, 0, 0, 0, 0, 512, 0};
        int kbases[7] = {0, 0, 512, 0, 0, 0, 0};
        int kts[7] = {16, 16, 16, 16, 48, 48, 48};
        int ofs = 0;
        for (int i = 0; i < 7; ++i) {
            J.src[i] = srcs[i]; J.dst[i] = dsts[i]; J.kpb[i] = kpbs[i];
            J.nbase[i] = nbases[i]; J.kbase[i] = kbases[i];
            J.ktiles[i] = kts[i]; J.tileofs[i] = ofs;
            ofs += kts[i] * 16;
        }
        transposeAll<<<ofs, dim3(32, 8)>>>(J);
    }

    const __half* x016 = N16 + (size_t)1024 * 8 * PANEL_H;

    // C0 = x0 @ W3 + b_xi (precedes PRE which folds it into P)
    {
        GemmArgs a = {};
        a.A[0] = x016;
        a.Bt = W3T; a.kpb = 8;
        a.bias0 = b_xi; a.out16a = C0;
        run_stream<MODE_C0>(a, 4, 64, 8, 1, 0);
    }
    // PRE: P[l] = el @ W2 + xl @ W4 + C0; streaming T=4 n-tiles per CTA
    {
        GemmArgs a = {};
        a.A[0] = E16; a.A[1] = N16;
        a.Bt = WpT; a.kpb = 16;
        a.C0 = C0;
        a.out16a = P;
        run_stream<MODE_PRE>(a, 1, 1024, 16, 4, 1);
    }

    for (int l = 0; l < Lsteps; ++l) {
        // xi gate -> X0H, XTH panels
        if (l == 0) {
            xi0_kernel<<<NH / 8 / 256, 256>>>(P, x016, N16, X0H16, XTH16);
        } else {
            GemmArgs a = {};
            a.A[0] = HX16;
            a.Bt = W1T; a.kpb = 8;
            a.P = P + (size_t)l * NH;
            a.x0 = x016; a.xl = N16 + (size_t)(l * 64) * 8 * PANEL_H;
            a.out16a = X0H16; a.out16b = XTH16;
            run_stream<MODE_XI>(a, 4, 64, 8, 1, 0);
        }
        // fused u | r: streaming T=2 (n = mem, mem+4) -> one wave of 256 CTAs
        {
            GemmArgs a = {};
            a.Bt = WurT; a.kpb = 24;
            a.bias0 = b_u; a.bias1 = b_r; a.hxp = HX16;
            a.out16a = U; a.out16b = RH16;
            if (l == 0) {
                a.A[0] = X0H16; a.A[1] = XTH16; a.kb0 = 8;
                run_stream<MODE_UR>(a, 4, 64, 16, 2, 4);
            } else {
                a.A[0] = HX16; a.A[1] = X0H16; a.A[2] = XTH16;
                run_stream<MODE_UR>(a, 4, 64, 24, 2, 4);
            }
        }
        // k + state update -> HX16 (+ fp32 d_out on final step)
        {
            GemmArgs a = {};
            a.A[0] = X0H16; a.A[1] = XTH16; a.A[2] = RH16;
            a.Bt = WkT; a.kpb = 24;
            a.bias0 = b_k; a.U = U; a.hxp = HX16;
            a.out16a = HX16;
            a.out0 = (l == Lsteps - 1) ? hx : nullptr;
            run_stream<MODE_K>(a, 4, 64, l == 0 ? 16 : 24, 1, 0);
        }
    }
}

// round 15
// speedup vs baseline: 1.0870x; 1.0870x over previous
#include <cuda_runtime.h>
#include <cuda_fp16.h>
#include <math.h>
#include <stdint.h>

// Problem constants
#define Hdim 512
#define Lsteps 16
#define Nrows 8192
#define NH (Nrows * Hdim)

// Panel: 128 rows x 64 fp16, 144B pitch (16B pad) = exact smem stage layout
#define PANEL_H 9216                    // halves per panel
#define PANEL_BYTES 18432
#define STG_BYTES 36864                 // A panel + B panel
#define NSTAGE 3
#define SMEM_BYTES (64 + NSTAGE * STG_BYTES)   // 110656

// ---------------- scratch (device globals) ------------------------------------
__device__ __half g_P[Lsteps * (size_t)NH];     // row-major, includes +C0
__device__ __half g_C0[NH];                     // row-major (x0@W3 + b_xi)
__device__ __half g_U[NH];                      // row-major
__device__ __half g_E16[75497472];              // panels
__device__ __half g_N16[80216064];              // panels (17 layers)
__device__ __half g_X0H16[4718592];
__device__ __half g_XTH16[4718592];
__device__ __half g_RH16[4718592];
__device__ __half g_HX16[4718592];              // fp16 recurrent state (panels)
__device__ __half g_W1T[294912];
__device__ __half g_WpT[589824];
__device__ __half g_W3T[294912];
__device__ __half g_WurT[1769472];
__device__ __half g_WkT[884736];

// ---------------- helpers -------------------------------------------------------
__device__ __forceinline__ uint32_t smem_u32(const void* p) {
    uint32_t a;
    asm("{ .reg .u64 t; cvta.to.shared.u64 t, %1; cvt.u32.u64 %0, t; }" : "=r"(a) : "l"(p));
    return a;
}
#define MBARRIER_INIT(addr, cnt) \
    asm volatile("mbarrier.init.shared.b64 [%0], %1;" :: "r"((uint32_t)(addr)), "r"((uint32_t)(cnt)) : "memory")
#define MBARRIER_EXPECT_TX(addr, tx) \
    asm volatile("mbarrier.arrive.expect_tx.shared.b64 _, [%0], %1;" :: "r"((uint32_t)(addr)), "r"((uint32_t)(tx)) : "memory")
#define MBARRIER_ARRIVE(addr) \
    asm volatile("mbarrier.arrive.shared.b64 _, [%0];" :: "r"((uint32_t)(addr)) : "memory")
#define MBARRIER_WAIT_PARITY(addr, par) do { \
    uint32_t _m = (uint32_t)(addr); uint32_t _p = (uint32_t)(par); uint32_t _d; \
    asm volatile("{\n\t.reg .pred p;\n\t" \
        "mbarrier.try_wait.parity.acquire.cta.shared::cta.b64 p, [%1], %2;\n\t" \
        "selp.b32 %0, 1, 0, p;\n\t}" : "=r"(_d) : "r"(_m), "r"(_p) : "memory"); \
    if (!_d) { \
        asm volatile("{\n\t.reg .pred P1;\n\t" \
            "WL_%=:\n\t" \
            "mbarrier.try_wait.parity.acquire.cta.shared::cta.b64 P1, [%0], %1, 0x989680;\n\t" \
            "@P1 bra.uni WD_%=;\n\t" \
            "bra.uni WL_%=;\n\t" \
            "WD_%=:\n\t}" :: "r"(_m), "r"(_p) : "memory"); \
    } } while (0)

__device__ __forceinline__ void bulk_cp(uint32_t dst, const void* src, uint32_t bytes,
                                        uint32_t mbar) {
    asm volatile(
        "cp.async.bulk.shared::cluster.global.mbarrier::complete_tx::bytes "
        "[%0], [%1], %2, [%3];"
        :: "r"(dst), "l"(src), "r"(bytes), "r"(mbar) : "memory");
}

__device__ __forceinline__ void ldsm_x4(uint32_t (&r)[4], uint32_t addr) {
    asm volatile("ldmatrix.sync.aligned.m8n8.x4.shared.b16 {%0,%1,%2,%3}, [%4];"
                 : "=r"(r[0]), "=r"(r[1]), "=r"(r[2]), "=r"(r[3]) : "r"(addr));
}
__device__ __forceinline__ void mma_f16(float (&d)[4], const uint32_t (&a)[4],
                                        uint32_t b0, uint32_t b1) {
    asm volatile(
        "mma.sync.aligned.m16n8k16.row.col.f32.f16.f16.f32 "
        "{%0,%1,%2,%3}, {%4,%5,%6,%7}, {%8,%9}, {%0,%1,%2,%3};"
        : "+f"(d[0]), "+f"(d[1]), "+f"(d[2]), "+f"(d[3])
        : "r"(a[0]), "r"(a[1]), "r"(a[2]), "r"(a[3]), "r"(b0), "r"(b1));
}
__device__ __forceinline__ float sigmoidf_(float x) { return 1.0f / (1.0f + expf(-x)); }
__device__ __forceinline__ float2 h2f(const __half* p) {
    return __half22float2(*(const __half2*)p);
}
__device__ __forceinline__ size_t pidx(int row, int col) {
    return ((size_t)((row >> 7) * 8 + (col >> 6))) * PANEL_H + (row & 127) * 72 + (col & 63);
}

// ---------------- GEMM ------------------------------------------------------------
struct GemmArgs {
    const __half* A[3];
    const __half* Bt;
    int kpb;
    int kb0;
    const __half* P;
    const __half* C0;
    const __half* x0;
    const __half* xl;
    const __half* hxp;
    const float* bias0;
    const float* bias1;
    const __half* U;
    float* out0;
    __half* out16a;
    __half* out16b;
};

#define MODE_PRE 0
#define MODE_C0  1
#define MODE_XI  2
#define MODE_UR  3
#define MODE_K   4

template <int MODE>
__device__ __forceinline__ void epi(const GemmArgs& g, int row, int col, float v0, float v1) {
    int c512 = col & 511;
    size_t idx = (size_t)row * Hdim + c512;
    if (MODE == MODE_PRE) {
        float2 c0v = h2f(g.C0 + (size_t)(row & (Nrows - 1)) * Hdim + c512);
        *(__half2*)(g.out16a + idx) = __floats2half2_rn(v0 + c0v.x, v1 + c0v.y);
    } else if (MODE == MODE_C0) {
        float2 b = *(const float2*)(g.bias0 + c512);
        *(__half2*)(g.out16a + idx) = __floats2half2_rn(v0 + b.x, v1 + b.y);
    } else if (MODE == MODE_XI) {
        size_t pp = pidx(row, c512);
        float2 p   = h2f(g.P  + idx);
        float2 x0v = h2f(g.x0 + pp);
        float2 xlv = h2f(g.xl + pp);
        float s0 = sigmoidf_(v0 + p.x);
        float s1 = sigmoidf_(v1 + p.y);
        *(__half2*)(g.out16a + pp) = __floats2half2_rn((1.f - s0) * x0v.x, (1.f - s1) * x0v.y);
        *(__half2*)(g.out16b + pp) = __floats2half2_rn(s0 * xlv.x, s1 * xlv.y);
    } else if (MODE == MODE_UR) {
        if (col < Hdim) {
            float2 b = *(const float2*)(g.bias0 + c512);
            *(__half2*)(g.out16a + idx) = __floats2half2_rn(sigmoidf_(v0 + b.x),
                                                            sigmoidf_(v1 + b.y));
        } else {
            size_t pp = pidx(row, c512);
            float2 b = *(const float2*)(g.bias1 + c512);
            float2 h = h2f(g.hxp + pp);
            *(__half2*)(g.out16b + pp) =
                __floats2half2_rn(sigmoidf_(v0 + b.x) * h.x, sigmoidf_(v1 + b.y) * h.y);
        }
    } else { // MODE_K
        size_t pp = pidx(row, c512);
        float2 b = *(const float2*)(g.bias0 + c512);
        float2 u = h2f(g.U + idx);
        float2 h = h2f(g.hxp + pp);
        float k0 = tanhf(v0 + b.x), k1 = tanhf(v1 + b.y);
        float r0 = (1.f - u.x) * k0 + u.x * h.x;
        float r1 = (1.f - u.y) * k1 + u.y * h.y;
        *(__half2*)(g.out16a + pp) = __floats2half2_rn(r0, r1);
        if (g.out0)
            *(float2*)(g.out0 + idx) = make_float2(r0, r1);
    }
}

__device__ __forceinline__ void issue_chunk(const GemmArgs& g, int kb, int m_tile, int n_tile,
                                            uint32_t dst, uint32_t mbar) {
    MBARRIER_EXPECT_TX(mbar, STG_BYTES);
    const __half* srcA = g.A[kb >> 3] + ((size_t)m_tile * 8 + (kb & 7)) * PANEL_H;
    const __half* srcB = g.Bt + ((size_t)n_tile * g.kpb + g.kb0 + kb) * PANEL_H;
    bulk_cp(dst, srcA, PANEL_BYTES, mbar);
    bulk_cp(dst + PANEL_BYTES, srcB, PANEL_BYTES, mbar);
}

__device__ __forceinline__ void compute_stage(uint32_t base, uint32_t a_off, uint32_t b_off,
                                              float (&acc)[4][4][4]) {
#pragma unroll
    for (int kk = 0; kk < 4; ++kk) {
        uint32_t a[4][4];
        uint32_t b[2][4];
#pragma unroll
        for (int i = 0; i < 4; ++i)
            ldsm_x4(a[i], base + a_off + kk * 32 + i * (16 * 144));
#pragma unroll
        for (int jj = 0; jj < 2; ++jj)
            ldsm_x4(b[jj], base + b_off + kk * 32 + jj * (16 * 144));
#pragma unroll
        for (int i = 0; i < 4; ++i)
#pragma unroll
            for (int j = 0; j < 4; ++j)
                mma_f16(acc[i][j], a[i], b[j >> 1][(j & 1) * 2], b[j >> 1][(j & 1) * 2 + 1]);
    }
}

// ---- streaming GEMM: T tiles per CTA, nested loops, incremental producer counters
template <int MODE>
__global__ void __launch_bounds__(256, 2) gemm_stream(GemmArgs args, int kblocks,
                                                      int T, int nstep) {
    extern __shared__ char sm[];
    uint32_t su = smem_u32(sm);
    int tid = threadIdx.x;
    int warp = tid >> 5, lane = tid & 31;
    int MW = (warp & 1) * 64, NW = (warp >> 1) * 32;
    int g = lane >> 2, c = lane & 3;
    int m_tile = blockIdx.y, n0 = blockIdx.x;
    int rowBase = m_tile * 128;

    if (tid == 0) {
        MBARRIER_INIT(su + 0, 1);  MBARRIER_INIT(su + 8, 1);  MBARRIER_INIT(su + 16, 1);
        MBARRIER_INIT(su + 24, 8); MBARRIER_INIT(su + 32, 8); MBARRIER_INIT(su + 40, 8);
    }
    __syncthreads();

    uint32_t a_off = (uint32_t)((MW + (lane & 15)) * 144 + (lane >> 4) * 16);
    uint32_t b_off = (uint32_t)(PANEL_BYTES + (NW + (lane & 7) + ((lane >> 4) << 3)) * 144
                                + ((lane >> 3) & 1) * 16);

    float acc[4][4][4];
#pragma unroll
    for (int i = 0; i < 4; ++i)
#pragma unroll
        for (int j = 0; j < 4; ++j)
#pragma unroll
            for (int e = 0; e < 4; ++e) acc[i][j][e] = 0.0f;

    // prologue: first NSTAGE kb chunks (kblocks >= 8 > NSTAGE, all within tile 0)
    if (tid == 0) {
#pragma unroll
        for (int s = 0; s < NSTAGE; ++s)
            issue_chunk(args, s, m_tile, n0, su + 64 + s * STG_BYTES, su + 8 * s);
    }

    int cs = 0, cp = 0;
    int ps = 0, pp = 0;
    int pt = 0, pkb = NSTAGE;   // next refill position (incremental; no div/mod)
    for (int t = 0; t < T; ++t) {
        for (int kb = 0; kb < kblocks; ++kb) {
            MBARRIER_WAIT_PARITY(su + 8 * cs, cp);
            compute_stage(su + 64 + cs * STG_BYTES, a_off, b_off, acc);
            if (lane == 0) MBARRIER_ARRIVE(su + 24 + 8 * cs);
            if (tid == 0 && pt < T) {
                MBARRIER_WAIT_PARITY(su + 24 + 8 * ps, pp);
                issue_chunk(args, pkb, m_tile, n0 + nstep * pt,
                            su + 64 + ps * STG_BYTES, su + 8 * ps);
                if (++ps == NSTAGE) { ps = 0; pp ^= 1; }
                if (++pkb == kblocks) { pkb = 0; ++pt; }
            }
            if (++cs == NSTAGE) { cs = 0; cp ^= 1; }
        }
        // epilogue for tile t (no modulo checks)
        int colBase = (n0 + nstep * t) * 128;
#pragma unroll
        for (int ii = 0; ii < 4; ++ii) {
#pragma unroll
            for (int j = 0; j < 4; ++j) {
                int row = rowBase + MW + ii * 16 + g;
                int col = colBase + NW + j * 8 + 2 * c;
                epi<MODE>(args, row, col, acc[ii][j][0], acc[ii][j][1]);
                epi<MODE>(args, row + 8, col, acc[ii][j][2], acc[ii][j][3]);
            }
        }
        if (t + 1 < T) {
#pragma unroll
            for (int ii = 0; ii < 4; ++ii)
#pragma unroll
                for (int j = 0; j < 4; ++j)
#pragma unroll
                    for (int e = 0; e < 4; ++e) acc[ii][j][e] = 0.0f;
        }
    }
}

// ---------------- step-0 XI elementwise (hx0 == 0 -> no GEMM) ---------------------
__global__ void xi0_kernel(const __half* __restrict__ P0,
                           const __half* __restrict__ x0p, const __half* __restrict__ xlp,
                           __half* __restrict__ X0H, __half* __restrict__ XTH) {
    int i = (blockIdx.x * blockDim.x + threadIdx.x) * 8;
    int row = i >> 9, col = i & 511;
    size_t pp = pidx(row, col);
    size_t idx = (size_t)row * Hdim + col;
    uint4 pv = *(const uint4*)(P0 + idx);
    uint4 xv = *(const uint4*)(x0p + pp);
    uint4 lv = *(const uint4*)(xlp + pp);
    const __half2* ph = (const __half2*)&pv;
    const __half2* xh = (const __half2*)&xv;
    const __half2* lh = (const __half2*)&lv;
    uint4 o0, o1;
    __half2* o0h = (__half2*)&o0;
    __half2* o1h = (__half2*)&o1;
#pragma unroll
    for (int q = 0; q < 4; ++q) {
        float2 p = __half22float2(ph[q]);
        float2 x = __half22float2(xh[q]);
        float2 l = __half22float2(lh[q]);
        float s0 = sigmoidf_(p.x);
        float s1 = sigmoidf_(p.y);
        o0h[q] = __floats2half2_rn((1.f - s0) * x.x, (1.f - s1) * x.y);
        o1h[q] = __floats2half2_rn(s0 * l.x, s1 * l.y);
    }
    *(uint4*)(X0H + pp) = o0;
    *(uint4*)(XTH + pp) = o1;
}

// ---------------- weight transpose into panels -----------------------------------
struct TransJobs {
    const float* src[7];
    __half* dst[7];
    int kpb[7];
    int nbase[7];
    int kbase[7];
    int ktiles[7];
    int tileofs[7];
};

__global__ void transposeAll(TransJobs J) {
    __shared__ float t[32][33];
    int bid = blockIdx.x;
    int job = 0;
#pragma unroll
    for (int i = 1; i < 7; ++i)
        if (bid >= J.tileofs[i]) job = i;
    int local = bid - J.tileofs[job];
    int kt = J.ktiles[job];
    int kb = (local % kt) * 32;
    int nb = (local / kt) * 32;
    const float* src = J.src[job];
    __half* dst = J.dst[job];
    int KPB = J.kpb[job];
    int tx = threadIdx.x, ty = threadIdx.y;
#pragma unroll
    for (int i = 0; i < 32; i += 8)
        t[ty + i][tx] = src[(size_t)(kb + ty + i) * 512 + nb + tx];
    __syncthreads();
    int k = J.kbase[job] + kb + tx;
#pragma unroll
    for (int i = 0; i < 32; i += 8) {
        int n = J.nbase[job] + nb + ty + i;
        size_t off = ((size_t)((n >> 7) * KPB + (k >> 6))) * PANEL_H + (n & 127) * 72 + (k & 63);
        dst[off] = __float2half_rn(t[tx][ty + i]);
    }
}

// ---------------- fp32 -> fp16 convert into panels --------------------------------
__global__ void f2h_panel(const float* __restrict__ src, __half* __restrict__ dst, int n) {
    int i = (blockIdx.x * blockDim.x + threadIdx.x) * 8;
    if (i >= n) return;
    float4 v0 = *(const float4*)(src + i);
    float4 v1 = *(const float4*)(src + i + 4);
    __half2 h[4] = {__floats2half2_rn(v0.x, v0.y), __floats2half2_rn(v0.z, v0.w),
                    __floats2half2_rn(v1.x, v1.y), __floats2half2_rn(v1.z, v1.w)};
    int row = i >> 9, col = i & 511;
    size_t off = ((size_t)((row >> 7) * 8 + (col >> 6))) * PANEL_H + (row & 127) * 72 + (col & 63);
    *(uint4*)(dst + off) = *(uint4*)h;
}

// ---------------- host --------------------------------------------------------------
template <int MODE>
static void run_stream(const GemmArgs& a, int gx, int gy, int kblocks, int T, int nstep) {
    cudaFuncSetAttribute(gemm_stream<MODE>, cudaFuncAttributeMaxDynamicSharedMemorySize,
                         SMEM_BYTES);
    dim3 grid(gx, gy);
    gemm_stream<MODE><<<grid, 256, SMEM_BYTES>>>(a, kblocks, T, nstep);
}

extern "C" void kernel_launch(void* const* d_in, const int* in_sizes, int n_in,
                              void* d_out, int out_size) {
    const float* edge = (const float*)d_in[0];
    const float* node = (const float*)d_in[1];
    const float* W_xi = (const float*)d_in[2];
    const float* b_xi = (const float*)d_in[3];
    const float* W_u  = (const float*)d_in[4];
    const float* b_u  = (const float*)d_in[5];
    const float* W_r  = (const float*)d_in[6];
    const float* b_r  = (const float*)d_in[7];
    const float* W_k  = (const float*)d_in[8];
    const float* b_k  = (const float*)d_in[9];
    float* hx = (float*)d_out;

    __half *P, *C0, *U;
    __half *E16, *N16, *X0H16, *XTH16, *RH16, *HX16, *W1T, *WpT, *W3T, *WurT, *WkT;
    cudaGetSymbolAddress((void**)&P,     g_P);
    cudaGetSymbolAddress((void**)&C0,    g_C0);
    cudaGetSymbolAddress((void**)&U,     g_U);
    cudaGetSymbolAddress((void**)&E16,   g_E16);
    cudaGetSymbolAddress((void**)&N16,   g_N16);
    cudaGetSymbolAddress((void**)&X0H16, g_X0H16);
    cudaGetSymbolAddress((void**)&XTH16, g_XTH16);
    cudaGetSymbolAddress((void**)&RH16,  g_RH16);
    cudaGetSymbolAddress((void**)&HX16,  g_HX16);
    cudaGetSymbolAddress((void**)&W1T,   g_W1T);
    cudaGetSymbolAddress((void**)&WpT,   g_WpT);
    cudaGetSymbolAddress((void**)&W3T,   g_W3T);
    cudaGetSymbolAddress((void**)&WurT,  g_WurT);
    cudaGetSymbolAddress((void**)&WkT,   g_WkT);

    cudaMemsetAsync(HX16, 0, sizeof(g_HX16), 0);

    // fp32 -> fp16 panels for edge / node (incl. x0)
    {
        int nE = Lsteps * NH;
        int nN = (Lsteps + 1) * NH;
        f2h_panel<<<(nE / 8 + 255) / 256, 256>>>(edge, E16, nE);
        f2h_panel<<<(nN / 8 + 255) / 256, 256>>>(node, N16, nN);
    }

    // weight transpose -> fp16 panels
    {
        TransJobs J;
        const float* srcs[7] = {W_xi, W_xi + 512 * 512, W_xi + 1536 * 512,
                                W_xi + 1024 * 512, W_u, W_r, W_k};
        __half* dsts[7] = {W1T, WpT, WpT, W3T, WurT, WurT, WkT};
        int kpbs[7]  = {8, 16, 16, 8, 24, 24, 24};
        int nbases[7] = {0, 0, 0, 0, 0, 512, 0};
        int kbases[7] = {0, 0, 512, 0, 0, 0, 0};
        int kts[7] = {16, 16, 16, 16, 48, 48, 48};
        int ofs = 0;
        for (int i = 0; i < 7; ++i) {
            J.src[i] = srcs[i]; J.dst[i] = dsts[i]; J.kpb[i] = kpbs[i];
            J.nbase[i] = nbases[i]; J.kbase[i] = kbases[i];
            J.ktiles[i] = kts[i]; J.tileofs[i] = ofs;
            ofs += kts[i] * 16;
        }
        transposeAll<<<ofs, dim3(32, 8)>>>(J);
    }

    const __half* x016 = N16 + (size_t)1024 * 8 * PANEL_H;

    // C0 = x0 @ W3 + b_xi (precedes PRE which folds it into P); T=1
    {
        GemmArgs a = {};
        a.A[0] = x016;
        a.Bt = W3T; a.kpb = 8;
        a.bias0 = b_xi; a.out16a = C0;
        run_stream<MODE_C0>(a, 4, 64, 8, 1, 0);
    }
    // PRE: P[l] = el @ W2 + xl @ W4 + C0; T=4 n-tiles streamed per CTA
    {
        GemmArgs a = {};
        a.A[0] = E16; a.A[1] = N16;
        a.Bt = WpT; a.kpb = 16;
        a.C0 = C0;
        a.out16a = P;
        run_stream<MODE_PRE>(a, 1, 1024, 16, 4, 1);
    }

    for (int l = 0; l < Lsteps; ++l) {
        // xi gate -> X0H, XTH panels (T=1)
        if (l == 0) {
            xi0_kernel<<<NH / 8 / 256, 256>>>(P, x016, N16, X0H16, XTH16);
        } else {
            GemmArgs a = {};
            a.A[0] = HX16;
            a.Bt = W1T; a.kpb = 8;
            a.P = P + (size_t)l * NH;
            a.x0 = x016; a.xl = N16 + (size_t)(l * 64) * 8 * PANEL_H;
            a.out16a = X0H16; a.out16b = XTH16;
            run_stream<MODE_XI>(a, 4, 64, 8, 1, 0);
        }
        // fused u | r: T=2 (n = g, g+4) -> one wave of 256 CTAs, single fill
        {
            GemmArgs a = {};
            a.Bt = WurT; a.kpb = 24;
            a.bias0 = b_u; a.bias1 = b_r; a.hxp = HX16;
            a.out16a = U; a.out16b = RH16;
            if (l == 0) {
                a.A[0] = X0H16; a.A[1] = XTH16; a.kb0 = 8;
                run_stream<MODE_UR>(a, 4, 64, 16, 2, 4);
            } else {
                a.A[0] = HX16; a.A[1] = X0H16; a.A[2] = XTH16;
                run_stream<MODE_UR>(a, 4, 64, 24, 2, 4);
            }
        }
        // k + state update -> HX16 (+ fp32 d_out on final step); T=1
        {
            GemmArgs a = {};
            a.A[0] = X0H16; a.A[1] = XTH16; a.A[2] = RH16;
            a.Bt = WkT; a.kpb = 24;
            a.bias0 = b_k; a.U = U; a.hxp = HX16;
            a.out16a = HX16;
            a.out0 = (l == Lsteps - 1) ? hx : nullptr;
            run_stream<MODE_K>(a, 4, 64, l == 0 ? 16 : 24, 1, 0);
        }
    }
}

// round 16
// speedup vs baseline: 1.1175x; 1.0281x over previous
#include <cuda_runtime.h>
#include <cuda_fp16.h>
#include <math.h>
#include <stdint.h>

// Problem constants
#define Hdim 512
#define Lsteps 16
#define Nrows 8192
#define NH (Nrows * Hdim)

// Panel: 128 rows x 64 fp16, 144B pitch (16B pad) = exact smem stage layout
#define PANEL_H 9216                    // halves per panel
#define PANEL_BYTES 18432
#define STG_BYTES 36864                 // A panel + B panel
#define NSTAGE 3
#define SMEM_BYTES (64 + NSTAGE * STG_BYTES)   // 110656

// ---------------- scratch (device globals) ------------------------------------
__device__ __half g_P[Lsteps * (size_t)NH];     // row-major, includes +C0
__device__ __half g_C0[NH];                     // row-major (x0@W3 + b_xi)
__device__ __half g_U[NH];                      // row-major
__device__ __half g_E16[75497472];              // panels
__device__ __half g_N16[80216064];              // panels (17 layers)
__device__ __half g_X0H16[4718592];
__device__ __half g_XTH16[4718592];
__device__ __half g_RH16[4718592];
__device__ __half g_HX16[4718592];              // fp16 recurrent state (panels)
__device__ __half g_W1T[294912];
__device__ __half g_WpT[589824];
__device__ __half g_W3T[294912];
__device__ __half g_WurT[1769472];
__device__ __half g_WkT[884736];

// ---------------- helpers -------------------------------------------------------
__device__ __forceinline__ uint32_t smem_u32(const void* p) {
    uint32_t a;
    asm("{ .reg .u64 t; cvta.to.shared.u64 t, %1; cvt.u32.u64 %0, t; }" : "=r"(a) : "l"(p));
    return a;
}
#define MBARRIER_INIT(addr, cnt) \
    asm volatile("mbarrier.init.shared.b64 [%0], %1;" :: "r"((uint32_t)(addr)), "r"((uint32_t)(cnt)) : "memory")
#define MBARRIER_EXPECT_TX(addr, tx) \
    asm volatile("mbarrier.arrive.expect_tx.shared.b64 _, [%0], %1;" :: "r"((uint32_t)(addr)), "r"((uint32_t)(tx)) : "memory")
#define MBARRIER_ARRIVE(addr) \
    asm volatile("mbarrier.arrive.shared.b64 _, [%0];" :: "r"((uint32_t)(addr)) : "memory")
#define MBARRIER_WAIT_PARITY(addr, par) do { \
    uint32_t _m = (uint32_t)(addr); uint32_t _p = (uint32_t)(par); uint32_t _d; \
    asm volatile("{\n\t.reg .pred p;\n\t" \
        "mbarrier.try_wait.parity.acquire.cta.shared::cta.b64 p, [%1], %2;\n\t" \
        "selp.b32 %0, 1, 0, p;\n\t}" : "=r"(_d) : "r"(_m), "r"(_p) : "memory"); \
    if (!_d) { \
        asm volatile("{\n\t.reg .pred P1;\n\t" \
            "WL_%=:\n\t" \
            "mbarrier.try_wait.parity.acquire.cta.shared::cta.b64 P1, [%0], %1, 0x989680;\n\t" \
            "@P1 bra.uni WD_%=;\n\t" \
            "bra.uni WL_%=;\n\t" \
            "WD_%=:\n\t}" :: "r"(_m), "r"(_p) : "memory"); \
    } } while (0)

__device__ __forceinline__ void bulk_cp(uint32_t dst, const void* src, uint32_t bytes,
                                        uint32_t mbar) {
    asm volatile(
        "cp.async.bulk.shared::cluster.global.mbarrier::complete_tx::bytes "
        "[%0], [%1], %2, [%3];"
        :: "r"(dst), "l"(src), "r"(bytes), "r"(mbar) : "memory");
}

__device__ __forceinline__ void ldsm_x4(uint32_t (&r)[4], uint32_t addr) {
    asm volatile("ldmatrix.sync.aligned.m8n8.x4.shared.b16 {%0,%1,%2,%3}, [%4];"
                 : "=r"(r[0]), "=r"(r[1]), "=r"(r[2]), "=r"(r[3]) : "r"(addr));
}
__device__ __forceinline__ void mma_f16(float (&d)[4], const uint32_t (&a)[4],
                                        uint32_t b0, uint32_t b1) {
    asm volatile(
        "mma.sync.aligned.m16n8k16.row.col.f32.f16.f16.f32 "
        "{%0,%1,%2,%3}, {%4,%5,%6,%7}, {%8,%9}, {%0,%1,%2,%3};"
        : "+f"(d[0]), "+f"(d[1]), "+f"(d[2]), "+f"(d[3])
        : "r"(a[0]), "r"(a[1]), "r"(a[2]), "r"(a[3]), "r"(b0), "r"(b1));
}
__device__ __forceinline__ float sigmoidf_(float x) { return 1.0f / (1.0f + expf(-x)); }
__device__ __forceinline__ float2 h2f(const __half* p) {
    return __half22float2(*(const __half2*)p);
}
__device__ __forceinline__ size_t pidx(int row, int col) {
    return ((size_t)((row >> 7) * 8 + (col >> 6))) * PANEL_H + (row & 127) * 72 + (col & 63);
}

// ---------------- GEMM ------------------------------------------------------------
struct GemmArgs {
    const __half* A[3];
    const __half* Bt;
    int kpb;
    int kb0;
    const __half* P;
    const __half* C0;
    const __half* x0;
    const __half* xl;
    const __half* hxp;
    const float* bias0;
    const float* bias1;
    const __half* U;
    float* out0;
    __half* out16a;
    __half* out16b;
};

#define MODE_PRE 0
#define MODE_C0  1
#define MODE_XI  2
#define MODE_UR  3
#define MODE_K   4

template <int MODE>
__device__ __forceinline__ void epi(const GemmArgs& g, int row, int col, float v0, float v1) {
    int c512 = col & 511;
    size_t idx = (size_t)row * Hdim + c512;
    if (MODE == MODE_PRE) {
        float2 c0v = h2f(g.C0 + (size_t)(row & (Nrows - 1)) * Hdim + c512);
        *(__half2*)(g.out16a + idx) = __floats2half2_rn(v0 + c0v.x, v1 + c0v.y);
    } else if (MODE == MODE_C0) {
        float2 b = *(const float2*)(g.bias0 + c512);
        *(__half2*)(g.out16a + idx) = __floats2half2_rn(v0 + b.x, v1 + b.y);
    } else if (MODE == MODE_XI) {
        size_t pp = pidx(row, c512);
        float2 p   = h2f(g.P  + idx);
        float2 x0v = h2f(g.x0 + pp);
        float2 xlv = h2f(g.xl + pp);
        float s0 = sigmoidf_(v0 + p.x);
        float s1 = sigmoidf_(v1 + p.y);
        *(__half2*)(g.out16a + pp) = __floats2half2_rn((1.f - s0) * x0v.x, (1.f - s1) * x0v.y);
        *(__half2*)(g.out16b + pp) = __floats2half2_rn(s0 * xlv.x, s1 * xlv.y);
    } else if (MODE == MODE_UR) {
        if (col < Hdim) {
            float2 b = *(const float2*)(g.bias0 + c512);
            *(__half2*)(g.out16a + idx) = __floats2half2_rn(sigmoidf_(v0 + b.x),
                                                            sigmoidf_(v1 + b.y));
        } else {
            size_t pp = pidx(row, c512);
            float2 b = *(const float2*)(g.bias1 + c512);
            float2 h = h2f(g.hxp + pp);
            *(__half2*)(g.out16b + pp) =
                __floats2half2_rn(sigmoidf_(v0 + b.x) * h.x, sigmoidf_(v1 + b.y) * h.y);
        }
    } else { // MODE_K
        size_t pp = pidx(row, c512);
        float2 b = *(const float2*)(g.bias0 + c512);
        float2 u = h2f(g.U + idx);
        float2 h = h2f(g.hxp + pp);
        float k0 = tanhf(v0 + b.x), k1 = tanhf(v1 + b.y);
        float r0 = (1.f - u.x) * k0 + u.x * h.x;
        float r1 = (1.f - u.y) * k1 + u.y * h.y;
        *(__half2*)(g.out16a + pp) = __floats2half2_rn(r0, r1);
        if (g.out0)
            *(float2*)(g.out0 + idx) = make_float2(r0, r1);
    }
}

__device__ __forceinline__ void issue_chunk(const GemmArgs& g, int kb, int m_tile, int n_tile,
                                            uint32_t dst, uint32_t mbar) {
    MBARRIER_EXPECT_TX(mbar, STG_BYTES);
    const __half* srcA = g.A[kb >> 3] + ((size_t)m_tile * 8 + (kb & 7)) * PANEL_H;
    const __half* srcB = g.Bt + ((size_t)n_tile * g.kpb + g.kb0 + kb) * PANEL_H;
    bulk_cp(dst, srcA, PANEL_BYTES, mbar);
    bulk_cp(dst + PANEL_BYTES, srcB, PANEL_BYTES, mbar);
}

__device__ __forceinline__ void compute_stage(uint32_t base, uint32_t a_off, uint32_t b_off,
                                              float (&acc)[4][4][4]) {
#pragma unroll
    for (int kk = 0; kk < 4; ++kk) {
        uint32_t a[4][4];
        uint32_t b[2][4];
#pragma unroll
        for (int i = 0; i < 4; ++i)
            ldsm_x4(a[i], base + a_off + kk * 32 + i * (16 * 144));
#pragma unroll
        for (int jj = 0; jj < 2; ++jj)
            ldsm_x4(b[jj], base + b_off + kk * 32 + jj * (16 * 144));
#pragma unroll
        for (int i = 0; i < 4; ++i)
#pragma unroll
            for (int j = 0; j < 4; ++j)
                mma_f16(acc[i][j], a[i], b[j >> 1][(j & 1) * 2], b[j >> 1][(j & 1) * 2 + 1]);
    }
}

template <int MODE>
__global__ void __launch_bounds__(256, 2) gemm_bulk(GemmArgs args, int kblocks) {
    extern __shared__ char sm[];
    uint32_t su = smem_u32(sm);
    int tid = threadIdx.x;
    int warp = tid >> 5, lane = tid & 31;
    int MW = (warp & 1) * 64, NW = (warp >> 1) * 32;
    int g = lane >> 2, c = lane & 3;
    int m_tile = blockIdx.y, n_tile = blockIdx.x;
    int rowBase = m_tile * 128, colBase = n_tile * 128;

    // full barriers at su+0/8/16 (count 1, tx); empty barriers at su+24/32/40 (count 8)
    if (tid == 0) {
        MBARRIER_INIT(su + 0, 1);  MBARRIER_INIT(su + 8, 1);  MBARRIER_INIT(su + 16, 1);
        MBARRIER_INIT(su + 24, 8); MBARRIER_INIT(su + 32, 8); MBARRIER_INIT(su + 40, 8);
    }
    __syncthreads();

    uint32_t a_off = (uint32_t)((MW + (lane & 15)) * 144 + (lane >> 4) * 16);
    uint32_t b_off = (uint32_t)(PANEL_BYTES + (NW + (lane & 7) + ((lane >> 4) << 3)) * 144
                                + ((lane >> 3) & 1) * 16);

    float acc[4][4][4];
#pragma unroll
    for (int i = 0; i < 4; ++i)
#pragma unroll
        for (int j = 0; j < 4; ++j)
#pragma unroll
            for (int e = 0; e < 4; ++e) acc[i][j][e] = 0.0f;

    if (tid == 0) {
        int ni = kblocks < NSTAGE ? kblocks : NSTAGE;
        for (int s = 0; s < ni; ++s)
            issue_chunk(args, s, m_tile, n_tile, su + 64 + s * STG_BYTES, su + 8 * s);
    }

    int cs = 0, cp = 0;      // consumer cursor on full barriers
    int ps = 0, pp = 0;      // producer cursor on empty barriers
    for (int kb = 0; kb < kblocks; ++kb) {
        MBARRIER_WAIT_PARITY(su + 8 * cs, cp);
        compute_stage(su + 64 + cs * STG_BYTES, a_off, b_off, acc);
        if (lane == 0) MBARRIER_ARRIVE(su + 24 + 8 * cs);
        if (tid == 0 && kb + NSTAGE < kblocks) {
            MBARRIER_WAIT_PARITY(su + 24 + 8 * ps, pp);
            issue_chunk(args, kb + NSTAGE, m_tile, n_tile,
                        su + 64 + ps * STG_BYTES, su + 8 * ps);
            if (++ps == NSTAGE) { ps = 0; pp ^= 1; }
        }
        if (++cs == NSTAGE) { cs = 0; cp ^= 1; }
    }

    // epilogue
#pragma unroll
    for (int i = 0; i < 4; ++i) {
#pragma unroll
        for (int j = 0; j < 4; ++j) {
            int row = rowBase + MW + i * 16 + g;
            int col = colBase + NW + j * 8 + 2 * c;
            epi<MODE>(args, row, col, acc[i][j][0], acc[i][j][1]);
            epi<MODE>(args, row + 8, col, acc[i][j][2], acc[i][j][3]);
        }
    }
}

// ---------------- step-0 XI elementwise (hx0 == 0 -> no GEMM) ---------------------
__global__ void xi0_kernel(const __half* __restrict__ P0,
                           const __half* __restrict__ x0p, const __half* __restrict__ xlp,
                           __half* __restrict__ X0H, __half* __restrict__ XTH) {
    int i = (blockIdx.x * blockDim.x + threadIdx.x) * 8;
    int row = i >> 9, col = i & 511;
    size_t pp = pidx(row, col);
    size_t idx = (size_t)row * Hdim + col;
    uint4 pv = *(const uint4*)(P0 + idx);       // P already includes C0
    uint4 xv = *(const uint4*)(x0p + pp);
    uint4 lv = *(const uint4*)(xlp + pp);
    const __half2* ph = (const __half2*)&pv;
    const __half2* xh = (const __half2*)&xv;
    const __half2* lh = (const __half2*)&lv;
    uint4 o0, o1;
    __half2* o0h = (__half2*)&o0;
    __half2* o1h = (__half2*)&o1;
#pragma unroll
    for (int q = 0; q < 4; ++q) {
        float2 p = __half22float2(ph[q]);
        float2 x = __half22float2(xh[q]);
        float2 l = __half22float2(lh[q]);
        float s0 = sigmoidf_(p.x);
        float s1 = sigmoidf_(p.y);
        o0h[q] = __floats2half2_rn((1.f - s0) * x.x, (1.f - s1) * x.y);
        o1h[q] = __floats2half2_rn(s0 * l.x, s1 * l.y);
    }
    *(uint4*)(X0H + pp) = o0;
    *(uint4*)(XTH + pp) = o1;
}

// ---------------- weight transpose into panels -----------------------------------
struct TransJobs {
    const float* src[7];
    __half* dst[7];
    int kpb[7];
    int nbase[7];
    int kbase[7];
    int ktiles[7];
    int tileofs[7];
};

__global__ void transposeAll(TransJobs J) {
    __shared__ float t[32][33];
    int bid = blockIdx.x;
    int job = 0;
#pragma unroll
    for (int i = 1; i < 7; ++i)
        if (bid >= J.tileofs[i]) job = i;
    int local = bid - J.tileofs[job];
    int kt = J.ktiles[job];
    int kb = (local % kt) * 32;
    int nb = (local / kt) * 32;
    const float* src = J.src[job];
    __half* dst = J.dst[job];
    int KPB = J.kpb[job];
    int tx = threadIdx.x, ty = threadIdx.y;
#pragma unroll
    for (int i = 0; i < 32; i += 8)
        t[ty + i][tx] = src[(size_t)(kb + ty + i) * 512 + nb + tx];
    __syncthreads();
    int k = J.kbase[job] + kb + tx;
#pragma unroll
    for (int i = 0; i < 32; i += 8) {
        int n = J.nbase[job] + nb + ty + i;
        size_t off = ((size_t)((n >> 7) * KPB + (k >> 6))) * PANEL_H + (n & 127) * 72 + (k & 63);
        dst[off] = __float2half_rn(t[tx][ty + i]);
    }
}

// ---------------- fp32 -> fp16 convert into panels --------------------------------
__global__ void f2h_panel(const float* __restrict__ src, __half* __restrict__ dst, int n) {
    int i = (blockIdx.x * blockDim.x + threadIdx.x) * 8;
    if (i >= n) return;
    float4 v0 = *(const float4*)(src + i);
    float4 v1 = *(const float4*)(src + i + 4);
    __half2 h[4] = {__floats2half2_rn(v0.x, v0.y), __floats2half2_rn(v0.z, v0.w),
                    __floats2half2_rn(v1.x, v1.y), __floats2half2_rn(v1.z, v1.w)};
    int row = i >> 9, col = i & 511;
    size_t off = ((size_t)((row >> 7) * 8 + (col >> 6))) * PANEL_H + (row & 127) * 72 + (col & 63);
    *(uint4*)(dst + off) = *(uint4*)h;
}

// ---------------- host --------------------------------------------------------------
template <int MODE>
static void run_gemm(const GemmArgs& a, int mTiles, int nTiles, int kblocks) {
    cudaFuncSetAttribute(gemm_bulk<MODE>, cudaFuncAttributeMaxDynamicSharedMemorySize,
                         SMEM_BYTES);
    dim3 grid(nTiles, mTiles);
    gemm_bulk<MODE><<<grid, 256, SMEM_BYTES>>>(a, kblocks);
}

extern "C" void kernel_launch(void* const* d_in, const int* in_sizes, int n_in,
                              void* d_out, int out_size) {
    const float* edge = (const float*)d_in[0];
    const float* node = (const float*)d_in[1];
    const float* W_xi = (const float*)d_in[2];
    const float* b_xi = (const float*)d_in[3];
    const float* W_u  = (const float*)d_in[4];
    const float* b_u  = (const float*)d_in[5];
    const float* W_r  = (const float*)d_in[6];
    const float* b_r  = (const float*)d_in[7];
    const float* W_k  = (const float*)d_in[8];
    const float* b_k  = (const float*)d_in[9];
    float* hx = (float*)d_out;

    __half *P, *C0, *U;
    __half *E16, *N16, *X0H16, *XTH16, *RH16, *HX16, *W1T, *WpT, *W3T, *WurT, *WkT;
    cudaGetSymbolAddress((void**)&P,     g_P);
    cudaGetSymbolAddress((void**)&C0,    g_C0);
    cudaGetSymbolAddress((void**)&U,     g_U);
    cudaGetSymbolAddress((void**)&E16,   g_E16);
    cudaGetSymbolAddress((void**)&N16,   g_N16);
    cudaGetSymbolAddress((void**)&X0H16, g_X0H16);
    cudaGetSymbolAddress((void**)&XTH16, g_XTH16);
    cudaGetSymbolAddress((void**)&RH16,  g_RH16);
    cudaGetSymbolAddress((void**)&HX16,  g_HX16);
    cudaGetSymbolAddress((void**)&W1T,   g_W1T);
    cudaGetSymbolAddress((void**)&WpT,   g_WpT);
    cudaGetSymbolAddress((void**)&W3T,   g_W3T);
    cudaGetSymbolAddress((void**)&WurT,  g_WurT);
    cudaGetSymbolAddress((void**)&WkT,   g_WkT);

    cudaMemsetAsync(HX16, 0, sizeof(g_HX16), 0);

    // fp32 -> fp16 panels for edge / node (incl. x0)
    {
        int nE = Lsteps * NH;
        int nN = (Lsteps + 1) * NH;
        f2h_panel<<<(nE / 8 + 255) / 256, 256>>>(edge, E16, nE);
        f2h_panel<<<(nN / 8 + 255) / 256, 256>>>(node, N16, nN);
    }

    // weight transpose -> fp16 panels
    {
        TransJobs J;
        const float* srcs[7] = {W_xi, W_xi + 512 * 512, W_xi + 1536 * 512,
                                W_xi + 1024 * 512, W_u, W_r, W_k};
        __half* dsts[7] = {W1T, WpT, WpT, W3T, WurT, WurT, WkT};
        int kpbs[7]  = {8, 16, 16, 8, 24, 24, 24};
        int nbases[7] = {0, 0, 0, 0, 0, 512, 0};
        int kbases[7] = {0, 0, 512, 0, 0, 0, 0};
        int kts[7] = {16, 16, 16, 16, 48, 48, 48};
        int ofs = 0;
        for (int i = 0; i < 7; ++i) {
            J.src[i] = srcs[i]; J.dst[i] = dsts[i]; J.kpb[i] = kpbs[i];
            J.nbase[i] = nbases[i]; J.kbase[i] = kbases[i];
            J.ktiles[i] = kts[i]; J.tileofs[i] = ofs;
            ofs += kts[i] * 16;
        }
        transposeAll<<<ofs, dim3(32, 8)>>>(J);
    }

    const __half* x016 = N16 + (size_t)1024 * 8 * PANEL_H;

    // C0 = x0 @ W3 + b_xi (precedes PRE which folds it into P)
    {
        GemmArgs a = {};
        a.A[0] = x016;
        a.Bt = W3T; a.kpb = 8;
        a.bias0 = b_xi; a.out16a = C0;
        run_gemm<MODE_C0>(a, 64, 4, 8);
    }
    // PRE: P[l] = el @ W2 + xl @ W4 + C0
    {
        GemmArgs a = {};
        a.A[0] = E16; a.A[1] = N16;
        a.Bt = WpT; a.kpb = 16;
        a.C0 = C0;
        a.out16a = P;
        run_gemm<MODE_PRE>(a, 1024, 4, 16);
    }

    for (int l = 0; l < Lsteps; ++l) {
        // xi gate -> X0H, XTH panels
        if (l == 0) {
            xi0_kernel<<<NH / 8 / 256, 256>>>(P, x016, N16, X0H16, XTH16);
        } else {
            GemmArgs a = {};
            a.A[0] = HX16;
            a.Bt = W1T; a.kpb = 8;
            a.P = P + (size_t)l * NH;
            a.x0 = x016; a.xl = N16 + (size_t)(l * 64) * 8 * PANEL_H;
            a.out16a = X0H16; a.out16b = XTH16;
            run_gemm<MODE_XI>(a, 64, 4, 8);
        }
        // fused u | r -> U (row-major), RH panels
        {
            GemmArgs a = {};
            a.Bt = WurT; a.kpb = 24;
            a.bias0 = b_u; a.bias1 = b_r; a.hxp = HX16;
            a.out16a = U; a.out16b = RH16;
            if (l == 0) {
                a.A[0] = X0H16; a.A[1] = XTH16; a.kb0 = 8;
                run_gemm<MODE_UR>(a, 64, 8, 16);
            } else {
                a.A[0] = HX16; a.A[1] = X0H16; a.A[2] = XTH16;
                run_gemm<MODE_UR>(a, 64, 8, 24);
            }
        }
        // k + state update -> HX16 (fp16 state), + fp32 d_out on final step
        {
            GemmArgs a = {};
            a.A[0] = X0H16; a.A[1] = XTH16; a.A[2] = RH16;
            a.Bt = WkT; a.kpb = 24;
            a.bias0 = b_k; a.U = U; a.hxp = HX16;
            a.out16a = HX16;
            a.out0 = (l == Lsteps - 1) ? hx : nullptr;
            run_gemm<MODE_K>(a, 64, 4, l == 0 ? 16 : 24);
        }
    }
}

// round 17
// speedup vs baseline: 1.1258x; 1.0074x over previous
#include <cuda_runtime.h>
#include <cuda_fp16.h>
#include <math.h>
#include <stdint.h>

// Problem constants
#define Hdim 512
#define Lsteps 16
#define Nrows 8192
#define NH (Nrows * Hdim)

// Panel: 128 rows x 64 fp16, 144B pitch (16B pad) = exact smem stage layout
#define PANEL_H 9216                    // halves per panel
#define PANEL_BYTES 18432
#define STG_BYTES 36864                 // A panel + B panel
#define NSTAGE 3
#define SMEM_BYTES (64 + NSTAGE * STG_BYTES)   // 110656

// ---------------- scratch (device globals) ------------------------------------
__device__ __half g_P[Lsteps * (size_t)NH];     // row-major, includes +C0
__device__ __half g_C0[NH];                     // row-major (x0@W3 + b_xi)
__device__ __half g_U[NH];                      // row-major
__device__ __half g_E16[75497472];              // panels
__device__ __half g_N16[80216064];              // panels (17 layers)
__device__ __half g_X0H16[4718592];
__device__ __half g_XTH16[4718592];
__device__ __half g_RH16[4718592];
__device__ __half g_HX16[4718592];              // fp16 recurrent state (panels)
__device__ __half g_W1T[294912];
__device__ __half g_WpT[589824];
__device__ __half g_W3T[294912];
__device__ __half g_WurT[1769472];
__device__ __half g_WkT[884736];

// ---------------- helpers -------------------------------------------------------
__device__ __forceinline__ uint32_t smem_u32(const void* p) {
    uint32_t a;
    asm("{ .reg .u64 t; cvta.to.shared.u64 t, %1; cvt.u32.u64 %0, t; }" : "=r"(a) : "l"(p));
    return a;
}
#define MBARRIER_INIT(addr, cnt) \
    asm volatile("mbarrier.init.shared.b64 [%0], %1;" :: "r"((uint32_t)(addr)), "r"((uint32_t)(cnt)) : "memory")
#define MBARRIER_EXPECT_TX(addr, tx) \
    asm volatile("mbarrier.arrive.expect_tx.shared.b64 _, [%0], %1;" :: "r"((uint32_t)(addr)), "r"((uint32_t)(tx)) : "memory")
#define MBARRIER_ARRIVE(addr) \
    asm volatile("mbarrier.arrive.shared.b64 _, [%0];" :: "r"((uint32_t)(addr)) : "memory")
#define MBARRIER_WAIT_PARITY(addr, par) do { \
    uint32_t _m = (uint32_t)(addr); uint32_t _p = (uint32_t)(par); uint32_t _d; \
    asm volatile("{\n\t.reg .pred p;\n\t" \
        "mbarrier.try_wait.parity.acquire.cta.shared::cta.b64 p, [%1], %2;\n\t" \
        "selp.b32 %0, 1, 0, p;\n\t}" : "=r"(_d) : "r"(_m), "r"(_p) : "memory"); \
    if (!_d) { \
        asm volatile("{\n\t.reg .pred P1;\n\t" \
            "WL_%=:\n\t" \
            "mbarrier.try_wait.parity.acquire.cta.shared::cta.b64 P1, [%0], %1, 0x989680;\n\t" \
            "@P1 bra.uni WD_%=;\n\t" \
            "bra.uni WL_%=;\n\t" \
            "WD_%=:\n\t}" :: "r"(_m), "r"(_p) : "memory"); \
    } } while (0)

__device__ __forceinline__ void bulk_cp(uint32_t dst, const void* src, uint32_t bytes,
                                        uint32_t mbar) {
    asm volatile(
        "cp.async.bulk.shared::cluster.global.mbarrier::complete_tx::bytes "
        "[%0], [%1], %2, [%3];"
        :: "r"(dst), "l"(src), "r"(bytes), "r"(mbar) : "memory");
}

__device__ __forceinline__ void ldsm_x4(uint32_t (&r)[4], uint32_t addr) {
    asm volatile("ldmatrix.sync.aligned.m8n8.x4.shared.b16 {%0,%1,%2,%3}, [%4];"
                 : "=r"(r[0]), "=r"(r[1]), "=r"(r[2]), "=r"(r[3]) : "r"(addr));
}
__device__ __forceinline__ void mma_f16(float (&d)[4], const uint32_t (&a)[4],
                                        uint32_t b0, uint32_t b1) {
    asm volatile(
        "mma.sync.aligned.m16n8k16.row.col.f32.f16.f16.f32 "
        "{%0,%1,%2,%3}, {%4,%5,%6,%7}, {%8,%9}, {%0,%1,%2,%3};"
        : "+f"(d[0]), "+f"(d[1]), "+f"(d[2]), "+f"(d[3])
        : "r"(a[0]), "r"(a[1]), "r"(a[2]), "r"(a[3]), "r"(b0), "r"(b1));
}
__device__ __forceinline__ float sigmoidf_(float x) { return 1.0f / (1.0f + expf(-x)); }
__device__ __forceinline__ float2 h2f(const __half* p) {
    return __half22float2(*(const __half2*)p);
}
__device__ __forceinline__ size_t pidx(int row, int col) {
    return ((size_t)((row >> 7) * 8 + (col >> 6))) * PANEL_H + (row & 127) * 72 + (col & 63);
}

// ---------------- GEMM ------------------------------------------------------------
struct GemmArgs {
    const __half* A[3];
    const __half* Bt;
    int kpb;
    int kb0;
    const __half* P;
    const __half* C0;
    const __half* x0;
    const __half* xl;
    const __half* hxp;          // fp16 state panels; nullptr => state is exactly 0 (l==0)
    const float* bias0;
    const float* bias1;
    const __half* U;
    float* out0;
    __half* out16a;
    __half* out16b;
};

#define MODE_PRE 0
#define MODE_C0  1
#define MODE_XI  2
#define MODE_UR  3
#define MODE_K   4

template <int MODE>
__device__ __forceinline__ void epi(const GemmArgs& g, int row, int col, float v0, float v1) {
    int c512 = col & 511;
    size_t idx = (size_t)row * Hdim + c512;
    if (MODE == MODE_PRE) {
        float2 c0v = h2f(g.C0 + (size_t)(row & (Nrows - 1)) * Hdim + c512);
        *(__half2*)(g.out16a + idx) = __floats2half2_rn(v0 + c0v.x, v1 + c0v.y);
    } else if (MODE == MODE_C0) {
        float2 b = *(const float2*)(g.bias0 + c512);
        *(__half2*)(g.out16a + idx) = __floats2half2_rn(v0 + b.x, v1 + b.y);
    } else if (MODE == MODE_XI) {
        size_t pp = pidx(row, c512);
        float2 p   = h2f(g.P  + idx);
        float2 x0v = h2f(g.x0 + pp);
        float2 xlv = h2f(g.xl + pp);
        float s0 = sigmoidf_(v0 + p.x);
        float s1 = sigmoidf_(v1 + p.y);
        *(__half2*)(g.out16a + pp) = __floats2half2_rn((1.f - s0) * x0v.x, (1.f - s1) * x0v.y);
        *(__half2*)(g.out16b + pp) = __floats2half2_rn(s0 * xlv.x, s1 * xlv.y);
    } else if (MODE == MODE_UR) {
        if (col < Hdim) {
            float2 b = *(const float2*)(g.bias0 + c512);
            *(__half2*)(g.out16a + idx) = __floats2half2_rn(sigmoidf_(v0 + b.x),
                                                            sigmoidf_(v1 + b.y));
        } else {
            size_t pp = pidx(row, c512);
            float2 b = *(const float2*)(g.bias1 + c512);
            float2 h = g.hxp ? h2f(g.hxp + pp) : make_float2(0.f, 0.f);
            *(__half2*)(g.out16b + pp) =
                __floats2half2_rn(sigmoidf_(v0 + b.x) * h.x, sigmoidf_(v1 + b.y) * h.y);
        }
    } else { // MODE_K
        size_t pp = pidx(row, c512);
        float2 b = *(const float2*)(g.bias0 + c512);
        float2 u = h2f(g.U + idx);
        float2 h = g.hxp ? h2f(g.hxp + pp) : make_float2(0.f, 0.f);
        float k0 = tanhf(v0 + b.x), k1 = tanhf(v1 + b.y);
        float r0 = (1.f - u.x) * k0 + u.x * h.x;
        float r1 = (1.f - u.y) * k1 + u.y * h.y;
        *(__half2*)(g.out16a + pp) = __floats2half2_rn(r0, r1);
        if (g.out0)
            *(float2*)(g.out0 + idx) = make_float2(r0, r1);
    }
}

__device__ __forceinline__ void issue_chunk(const GemmArgs& g, int kb, int m_tile, int n_tile,
                                            uint32_t dst, uint32_t mbar) {
    MBARRIER_EXPECT_TX(mbar, STG_BYTES);
    const __half* srcA = g.A[kb >> 3] + ((size_t)m_tile * 8 + (kb & 7)) * PANEL_H;
    const __half* srcB = g.Bt + ((size_t)n_tile * g.kpb + g.kb0 + kb) * PANEL_H;
    bulk_cp(dst, srcA, PANEL_BYTES, mbar);
    bulk_cp(dst + PANEL_BYTES, srcB, PANEL_BYTES, mbar);
}

__device__ __forceinline__ void compute_stage(uint32_t base, uint32_t a_off, uint32_t b_off,
                                              float (&acc)[4][4][4]) {
#pragma unroll
    for (int kk = 0; kk < 4; ++kk) {
        uint32_t a[4][4];
        uint32_t b[2][4];
#pragma unroll
        for (int i = 0; i < 4; ++i)
            ldsm_x4(a[i], base + a_off + kk * 32 + i * (16 * 144));
#pragma unroll
        for (int jj = 0; jj < 2; ++jj)
            ldsm_x4(b[jj], base + b_off + kk * 32 + jj * (16 * 144));
#pragma unroll
        for (int i = 0; i < 4; ++i)
#pragma unroll
            for (int j = 0; j < 4; ++j)
                mma_f16(acc[i][j], a[i], b[j >> 1][(j & 1) * 2], b[j >> 1][(j & 1) * 2 + 1]);
    }
}

template <int MODE>
__global__ void __launch_bounds__(256, 2) gemm_bulk(GemmArgs args, int kblocks) {
    extern __shared__ char sm[];
    uint32_t su = smem_u32(sm);
    int tid = threadIdx.x;
    int warp = tid >> 5, lane = tid & 31;
    int MW = (warp & 1) * 64, NW = (warp >> 1) * 32;
    int g = lane >> 2, c = lane & 3;
    int m_tile = blockIdx.y, n_tile = blockIdx.x;
    int rowBase = m_tile * 128, colBase = n_tile * 128;

    // full barriers at su+0/8/16 (count 1, tx); empty barriers at su+24/32/40 (count 8)
    if (tid == 0) {
        MBARRIER_INIT(su + 0, 1);  MBARRIER_INIT(su + 8, 1);  MBARRIER_INIT(su + 16, 1);
        MBARRIER_INIT(su + 24, 8); MBARRIER_INIT(su + 32, 8); MBARRIER_INIT(su + 40, 8);
    }
    __syncthreads();

    uint32_t a_off = (uint32_t)((MW + (lane & 15)) * 144 + (lane >> 4) * 16);
    uint32_t b_off = (uint32_t)(PANEL_BYTES + (NW + (lane & 7) + ((lane >> 4) << 3)) * 144
                                + ((lane >> 3) & 1) * 16);

    float acc[4][4][4];
#pragma unroll
    for (int i = 0; i < 4; ++i)
#pragma unroll
        for (int j = 0; j < 4; ++j)
#pragma unroll
            for (int e = 0; e < 4; ++e) acc[i][j][e] = 0.0f;

    if (tid == 0) {
        int ni = kblocks < NSTAGE ? kblocks : NSTAGE;
        for (int s = 0; s < ni; ++s)
            issue_chunk(args, s, m_tile, n_tile, su + 64 + s * STG_BYTES, su + 8 * s);
    }

    int cs = 0, cp = 0;      // consumer cursor on full barriers
    int ps = 0, pp = 0;      // producer cursor on empty barriers
    for (int kb = 0; kb < kblocks; ++kb) {
        MBARRIER_WAIT_PARITY(su + 8 * cs, cp);
        compute_stage(su + 64 + cs * STG_BYTES, a_off, b_off, acc);
        if (lane == 0) MBARRIER_ARRIVE(su + 24 + 8 * cs);
        if (tid == 0 && kb + NSTAGE < kblocks) {
            MBARRIER_WAIT_PARITY(su + 24 + 8 * ps, pp);
            issue_chunk(args, kb + NSTAGE, m_tile, n_tile,
                        su + 64 + ps * STG_BYTES, su + 8 * ps);
            if (++ps == NSTAGE) { ps = 0; pp ^= 1; }
        }
        if (++cs == NSTAGE) { cs = 0; cp ^= 1; }
    }

    // epilogue
#pragma unroll
    for (int i = 0; i < 4; ++i) {
#pragma unroll
        for (int j = 0; j < 4; ++j) {
            int row = rowBase + MW + i * 16 + g;
            int col = colBase + NW + j * 8 + 2 * c;
            epi<MODE>(args, row, col, acc[i][j][0], acc[i][j][1]);
            epi<MODE>(args, row + 8, col, acc[i][j][2], acc[i][j][3]);
        }
    }
}

// ---------------- step-0 XI elementwise (hx0 == 0 -> no GEMM) ---------------------
__global__ void xi0_kernel(const __half* __restrict__ P0,
                           const __half* __restrict__ x0p, const __half* __restrict__ xlp,
                           __half* __restrict__ X0H, __half* __restrict__ XTH) {
    int i = (blockIdx.x * blockDim.x + threadIdx.x) * 8;
    int row = i >> 9, col = i & 511;
    size_t pp = pidx(row, col);
    size_t idx = (size_t)row * Hdim + col;
    uint4 pv = *(const uint4*)(P0 + idx);       // P already includes C0
    uint4 xv = *(const uint4*)(x0p + pp);
    uint4 lv = *(const uint4*)(xlp + pp);
    const __half2* ph = (const __half2*)&pv;
    const __half2* xh = (const __half2*)&xv;
    const __half2* lh = (const __half2*)&lv;
    uint4 o0, o1;
    __half2* o0h = (__half2*)&o0;
    __half2* o1h = (__half2*)&o1;
#pragma unroll
    for (int q = 0; q < 4; ++q) {
        float2 p = __half22float2(ph[q]);
        float2 x = __half22float2(xh[q]);
        float2 l = __half22float2(lh[q]);
        float s0 = sigmoidf_(p.x);
        float s1 = sigmoidf_(p.y);
        o0h[q] = __floats2half2_rn((1.f - s0) * x.x, (1.f - s1) * x.y);
        o1h[q] = __floats2half2_rn(s0 * l.x, s1 * l.y);
    }
    *(uint4*)(X0H + pp) = o0;
    *(uint4*)(XTH + pp) = o1;
}

// ---------------- weight transpose into panels -----------------------------------
struct TransJobs {
    const float* src[7];
    __half* dst[7];
    int kpb[7];
    int nbase[7];
    int kbase[7];
    int ktiles[7];
    int tileofs[7];
};

__global__ void transposeAll(TransJobs J) {
    __shared__ float t[32][33];
    int bid = blockIdx.x;
    int job = 0;
#pragma unroll
    for (int i = 1; i < 7; ++i)
        if (bid >= J.tileofs[i]) job = i;
    int local = bid - J.tileofs[job];
    int kt = J.ktiles[job];
    int kb = (local % kt) * 32;
    int nb = (local / kt) * 32;
    const float* src = J.src[job];
    __half* dst = J.dst[job];
    int KPB = J.kpb[job];
    int tx = threadIdx.x, ty = threadIdx.y;
#pragma unroll
    for (int i = 0; i < 32; i += 8)
        t[ty + i][tx] = src[(size_t)(kb + ty + i) * 512 + nb + tx];
    __syncthreads();
    int k = J.kbase[job] + kb + tx;
#pragma unroll
    for (int i = 0; i < 32; i += 8) {
        int n = J.nbase[job] + nb + ty + i;
        size_t off = ((size_t)((n >> 7) * KPB + (k >> 6))) * PANEL_H + (n & 127) * 72 + (k & 63);
        dst[off] = __float2half_rn(t[tx][ty + i]);
    }
}

// ---------------- fp32 -> fp16 convert into panels --------------------------------
__global__ void f2h_panel(const float* __restrict__ src, __half* __restrict__ dst, int n) {
    int i = (blockIdx.x * blockDim.x + threadIdx.x) * 8;
    if (i >= n) return;
    float4 v0 = *(const float4*)(src + i);
    float4 v1 = *(const float4*)(src + i + 4);
    __half2 h[4] = {__floats2half2_rn(v0.x, v0.y), __floats2half2_rn(v0.z, v0.w),
                    __floats2half2_rn(v1.x, v1.y), __floats2half2_rn(v1.z, v1.w)};
    int row = i >> 9, col = i & 511;
    size_t off = ((size_t)((row >> 7) * 8 + (col >> 6))) * PANEL_H + (row & 127) * 72 + (col & 63);
    *(uint4*)(dst + off) = *(uint4*)h;
}

// ---------------- host --------------------------------------------------------------
template <int MODE>
static void run_gemm(const GemmArgs& a, int mTiles, int nTiles, int kblocks) {
    cudaFuncSetAttribute(gemm_bulk<MODE>, cudaFuncAttributeMaxDynamicSharedMemorySize,
                         SMEM_BYTES);
    dim3 grid(nTiles, mTiles);
    gemm_bulk<MODE><<<grid, 256, SMEM_BYTES>>>(a, kblocks);
}

extern "C" void kernel_launch(void* const* d_in, const int* in_sizes, int n_in,
                              void* d_out, int out_size) {
    const float* edge = (const float*)d_in[0];
    const float* node = (const float*)d_in[1];
    const float* W_xi = (const float*)d_in[2];
    const float* b_xi = (const float*)d_in[3];
    const float* W_u  = (const float*)d_in[4];
    const float* b_u  = (const float*)d_in[5];
    const float* W_r  = (const float*)d_in[6];
    const float* b_r  = (const float*)d_in[7];
    const float* W_k  = (const float*)d_in[8];
    const float* b_k  = (const float*)d_in[9];
    float* hx = (float*)d_out;

    __half *P, *C0, *U;
    __half *E16, *N16, *X0H16, *XTH16, *RH16, *HX16, *W1T, *WpT, *W3T, *WurT, *WkT;
    cudaGetSymbolAddress((void**)&P,     g_P);
    cudaGetSymbolAddress((void**)&C0,    g_C0);
    cudaGetSymbolAddress((void**)&U,     g_U);
    cudaGetSymbolAddress((void**)&E16,   g_E16);
    cudaGetSymbolAddress((void**)&N16,   g_N16);
    cudaGetSymbolAddress((void**)&X0H16, g_X0H16);
    cudaGetSymbolAddress((void**)&XTH16, g_XTH16);
    cudaGetSymbolAddress((void**)&RH16,  g_RH16);
    cudaGetSymbolAddress((void**)&HX16,  g_HX16);
    cudaGetSymbolAddress((void**)&W1T,   g_W1T);
    cudaGetSymbolAddress((void**)&WpT,   g_WpT);
    cudaGetSymbolAddress((void**)&W3T,   g_W3T);
    cudaGetSymbolAddress((void**)&WurT,  g_WurT);
    cudaGetSymbolAddress((void**)&WkT,   g_WkT);

    // fp32 -> fp16 panels for edge / node (incl. x0)
    {
        int nE = Lsteps * NH;
        int nN = (Lsteps + 1) * NH;
        f2h_panel<<<(nE / 8 + 255) / 256, 256>>>(edge, E16, nE);
        f2h_panel<<<(nN / 8 + 255) / 256, 256>>>(node, N16, nN);
    }

    // weight transpose -> fp16 panels
    {
        TransJobs J;
        const float* srcs[7] = {W_xi, W_xi + 512 * 512, W_xi + 1536 * 512,
                                W_xi + 1024 * 512, W_u, W_r, W_k};
        __half* dsts[7] = {W1T, WpT, WpT, W3T, WurT, WurT, WkT};
        int kpbs[7]  = {8, 16, 16, 8, 24, 24, 24};
        int nbases[7] = {0, 0, 0, 0, 0, 512, 0};
        int kbases[7] = {0, 0, 512, 0, 0, 0, 0};
        int kts[7] = {16, 16, 16, 16, 48, 48, 48};
        int ofs = 0;
        for (int i = 0; i < 7; ++i) {
            J.src[i] = srcs[i]; J.dst[i] = dsts[i]; J.kpb[i] = kpbs[i];
            J.nbase[i] = nbases[i]; J.kbase[i] = kbases[i];
            J.ktiles[i] = kts[i]; J.tileofs[i] = ofs;
            ofs += kts[i] * 16;
        }
        transposeAll<<<ofs, dim3(32, 8)>>>(J);
    }

    const __half* x016 = N16 + (size_t)1024 * 8 * PANEL_H;

    // C0 = x0 @ W3 + b_xi (precedes PRE which folds it into P)
    {
        GemmArgs a = {};
        a.A[0] = x016;
        a.Bt = W3T; a.kpb = 8;
        a.bias0 = b_xi; a.out16a = C0;
        run_gemm<MODE_C0>(a, 64, 4, 8);
    }
    // PRE: P[l] = el @ W2 + xl @ W4 + C0
    {
        GemmArgs a = {};
        a.A[0] = E16; a.A[1] = N16;
        a.Bt = WpT; a.kpb = 16;
        a.C0 = C0;
        a.out16a = P;
        run_gemm<MODE_PRE>(a, 1024, 4, 16);
    }

    for (int l = 0; l < Lsteps; ++l) {
        // xi gate -> X0H, XTH panels
        if (l == 0) {
            xi0_kernel<<<NH / 8 / 256, 256>>>(P, x016, N16, X0H16, XTH16);
        } else {
            GemmArgs a = {};
            a.A[0] = HX16;
            a.Bt = W1T; a.kpb = 8;
            a.P = P + (size_t)l * NH;
            a.x0 = x016; a.xl = N16 + (size_t)(l * 64) * 8 * PANEL_H;
            a.out16a = X0H16; a.out16b = XTH16;
            run_gemm<MODE_XI>(a, 64, 4, 8);
        }
        // fused u | r -> U (row-major), RH panels
        {
            GemmArgs a = {};
            a.Bt = WurT; a.kpb = 24;
            a.bias0 = b_u; a.bias1 = b_r;
            a.out16a = U; a.out16b = RH16;
            if (l == 0) {
                // hx0 == 0: skip hx K-block; hxp = nullptr -> RH written as exact 0
                a.A[0] = X0H16; a.A[1] = XTH16; a.kb0 = 8;
                a.hxp = nullptr;
                run_gemm<MODE_UR>(a, 64, 8, 16);
            } else {
                a.A[0] = HX16; a.A[1] = X0H16; a.A[2] = XTH16;
                a.hxp = HX16;
                run_gemm<MODE_UR>(a, 64, 8, 24);
            }
        }
        // k + state update -> HX16 (fp16 state), + fp32 d_out on final step
        {
            GemmArgs a = {};
            a.A[0] = X0H16; a.A[1] = XTH16; a.A[2] = RH16;
            a.Bt = WkT; a.kpb = 24;
            a.bias0 = b_k; a.U = U;
            a.hxp = (l == 0) ? nullptr : HX16;   // l==0: u*hx0 term is exactly 0
            a.out16a = HX16;
            a.out0 = (l == Lsteps - 1) ? hx : nullptr;
            run_gemm<MODE_K>(a, 64, 4, l == 0 ? 16 : 24);
        }
    }
}